// round 13
// baseline (speedup 1.0000x reference)
#include <cuda_runtime.h>
#include <cstdint>

// Shapes (fixed by the problem)
#define S_IN   2048
#define S_T    2048
#define BATCH  8
#define HID    64

#define TM      16           // t-rows per CTA
#define THREADS 256          // 8 warps; warp w owns cols {p*128 + w*16 .. +15}, p=0..15
#define NPASS   16
#define SSP     2056         // sS pitch (floats)
#define LPITCH  68           // sWT staging pitch
#define BP      68           // per-warp B staging pitch (conflict-free frag LDS)

// SMEM (floats): sS[16][SSP] | sP[16][64] | stage[8 warps][16][BP]
#define SS_FLOATS   (TM * SSP)
#define SP_OFF      SS_FLOATS
#define STAGE_OFF   (SP_OFF + TM * HID)
#define SMEM_FLOATS (STAGE_OFF + 8 * 16 * BP)

__device__ __forceinline__ float tf32_hi(float x) {
    uint32_t u;
    asm("cvt.rna.tf32.f32 %0, %1;" : "=r"(u) : "f"(x));
    return __uint_as_float(u);
}

// D = A(16x8,row) * B(8x8,col) + D, tf32 inputs, f32 accum
__device__ __forceinline__ void mma8(float c[4], const float a[4], float b0, float b1) {
    asm volatile(
        "mma.sync.aligned.m16n8k8.row.col.f32.tf32.tf32.f32 "
        "{%0,%1,%2,%3}, {%4,%5,%6,%7}, {%8,%9}, {%0,%1,%2,%3};"
        : "+f"(c[0]), "+f"(c[1]), "+f"(c[2]), "+f"(c[3])
        : "r"(__float_as_uint(a[0])), "r"(__float_as_uint(a[1])),
          "r"(__float_as_uint(a[2])), "r"(__float_as_uint(a[3])),
          "r"(__float_as_uint(b0)),  "r"(__float_as_uint(b1)));
}

__device__ __forceinline__ float warp_sum(float v) {
    v += __shfl_xor_sync(0xffffffffu, v, 16);
    v += __shfl_xor_sync(0xffffffffu, v, 8);
    v += __shfl_xor_sync(0xffffffffu, v, 4);
    v += __shfl_xor_sync(0xffffffffu, v, 2);
    v += __shfl_xor_sync(0xffffffffu, v, 1);
    return v;
}
__device__ __forceinline__ float warp_max(float v) {
    v = fmaxf(v, __shfl_xor_sync(0xffffffffu, v, 16));
    v = fmaxf(v, __shfl_xor_sync(0xffffffffu, v, 8));
    v = fmaxf(v, __shfl_xor_sync(0xffffffffu, v, 4));
    v = fmaxf(v, __shfl_xor_sync(0xffffffffu, v, 2));
    v = fmaxf(v, __shfl_xor_sync(0xffffffffu, v, 1));
    return v;
}

__global__ void __launch_bounds__(THREADS, 1)
attn_mma_kernel(const float* __restrict__ inp,        // (S_IN, B, H)
                const float* __restrict__ tgt,        // (S_T, B, H)
                const unsigned char* __restrict__ msk,// (B, S_T, S_IN) bool
                const float* __restrict__ Wm,         // (H, H)  W[o][h]
                const float* __restrict__ bias,       // (H)
                float* __restrict__ out)              // (B, S_T, S_IN)
{
    extern __shared__ float sm[];
    float* sS = sm;                     // scores, pitch SSP
    float* sP = sm + SP_OFF;            // P = tgt_tile @ W^T + b, [16][64]
    float* sStage = sm + STAGE_OFF;     // per-warp B slots [16][BP]

    const int tid  = threadIdx.x;
    const int w    = tid >> 5;
    const int l    = tid & 31;
    const int b    = blockIdx.x >> 7;
    const int t0   = (blockIdx.x & 127) << 4;

    // ---------------- linear stage: P = tgt_tile @ W^T + bias -----------------
    {
        float* sWT = sS;                 // [64][LPITCH]
        float* sTg = sS + HID * LPITCH;  // [16][64]
        const int o  = tid >> 2;
        const int hq = (tid & 3) * 16;
        #pragma unroll
        for (int k = 0; k < 4; ++k) {
            float4 wv = *reinterpret_cast<const float4*>(Wm + o * HID + hq + 4 * k);
            sWT[(hq + 4 * k + 0) * LPITCH + o] = wv.x;
            sWT[(hq + 4 * k + 1) * LPITCH + o] = wv.y;
            sWT[(hq + 4 * k + 2) * LPITCH + o] = wv.z;
            sWT[(hq + 4 * k + 3) * LPITCH + o] = wv.w;
        }
        const int r  = tid >> 4;
        const int hh = (tid & 15) * 4;
        *reinterpret_cast<float4*>(sTg + r * HID + hh) =
            *reinterpret_cast<const float4*>(tgt + ((size_t)((t0 + r) * BATCH + b)) * HID + hh);
        __syncthreads();

        const int o0 = (tid & 15) * 4;
        float4 acc = *reinterpret_cast<const float4*>(bias + o0);
        #pragma unroll
        for (int h = 0; h < HID; ++h) {
            const float  tv = sTg[r * HID + h];
            const float4 wv = *reinterpret_cast<const float4*>(sWT + h * LPITCH + o0);
            acc.x += tv * wv.x;
            acc.y += tv * wv.y;
            acc.z += tv * wv.z;
            acc.w += tv * wv.w;
        }
        *reinterpret_cast<float4*>(sP + r * HID + o0) = acc;
        __syncthreads();   // P visible; sS region free for scores
    }

    // ---------------- preload A fragments (hi/lo tf32 split) ------------------
    float ah[8][4], al[8][4];
    {
        const float* p0 = sP + (l >> 2) * HID;
        const float* p1 = p0 + 8 * HID;
        #pragma unroll
        for (int kk = 0; kk < 8; ++kk) {
            const int k0 = kk * 8 + (l & 3);
            const float a0 = p0[k0], a1 = p1[k0], a2 = p0[k0 + 4], a3 = p1[k0 + 4];
            ah[kk][0] = tf32_hi(a0); al[kk][0] = a0 - ah[kk][0];
            ah[kk][1] = tf32_hi(a1); al[kk][1] = a1 - ah[kk][1];
            ah[kk][2] = tf32_hi(a2); al[kk][2] = a2 - ah[kk][2];
            ah[kk][3] = tf32_hi(a3); al[kk][3] = a3 - ah[kk][3];
        }
    }

    // ---------------- score GEMM: 16 passes of 16 s-cols per warp -------------
    float* slot = sStage + w * (16 * BP);
    const int srow2 = l >> 1;            // staging s-row 0..15
    const int shalf = (l & 1) * 32;      // 32-float half of the 64-float row

    float4 pf[8];
    {   // prefetch pass 0: s = w*16 + srow2
        const float4* src = reinterpret_cast<const float4*>(
            inp + ((size_t)((w * 16 + srow2) * BATCH + b)) * HID + shalf);
        #pragma unroll
        for (int q = 0; q < 8; ++q) pf[q] = src[q];
    }

    #pragma unroll 2
    for (int p = 0; p < NPASS; ++p) {
        __syncwarp();                    // prior frag LDS done before overwrite
        #pragma unroll
        for (int q = 0; q < 8; ++q)
            *reinterpret_cast<float4*>(slot + srow2 * BP + shalf + 4 * q) = pf[q];
        __syncwarp();
        if (p + 1 < NPASS) {             // prefetch next pass under the MMAs
            const int s = (p + 1) * 128 + w * 16 + srow2;
            const float4* src = reinterpret_cast<const float4*>(
                inp + ((size_t)(s * BATCH + b)) * HID + shalf);
            #pragma unroll
            for (int q = 0; q < 8; ++q) pf[q] = src[q];
        }

        // 6 independent accumulator chains: 2 col-tiles x 3 split-combos
        float chh[2][4], clh[2][4], chl[2][4];
        #pragma unroll
        for (int t = 0; t < 2; ++t)
            #pragma unroll
            for (int i = 0; i < 4; ++i) { chh[t][i] = 0.f; clh[t][i] = 0.f; chl[t][i] = 0.f; }

        const float* bp0 = slot + (l >> 2) * BP + (l & 3);        // tile 0 frag base
        const float* bp1 = bp0 + 8 * BP;                          // tile 1 frag base
        #pragma unroll
        for (int kk = 0; kk < 8; ++kk) {
            const float b00 = bp0[kk * 8],     b01 = bp0[kk * 8 + 4];
            const float b10 = bp1[kk * 8],     b11 = bp1[kk * 8 + 4];
            const float b00h = tf32_hi(b00), b00l = b00 - b00h;
            const float b01h = tf32_hi(b01), b01l = b01 - b01h;
            const float b10h = tf32_hi(b10), b10l = b10 - b10h;
            const float b11h = tf32_hi(b11), b11l = b11 - b11h;
            mma8(chh[0], ah[kk], b00h, b01h);
            mma8(chh[1], ah[kk], b10h, b11h);
            mma8(clh[0], al[kk], b00h, b01h);
            mma8(clh[1], al[kk], b10h, b11h);
            mma8(chl[0], ah[kk], b00l, b01l);
            mma8(chl[1], ah[kk], b10l, b11l);
        }

        // combine splits + store: rows l/4 and l/4+8, cols base + t*8 + 2*(l%4)
        #pragma unroll
        for (int t = 0; t < 2; ++t) {
            const float c0 = chh[t][0] + clh[t][0] + chl[t][0];
            const float c1 = chh[t][1] + clh[t][1] + chl[t][1];
            const float c2 = chh[t][2] + clh[t][2] + chl[t][2];
            const float c3 = chh[t][3] + clh[t][3] + chl[t][3];
            float* dst = sS + (l >> 2) * SSP + p * 128 + w * 16 + t * 8 + 2 * (l & 3);
            *reinterpret_cast<float2*>(dst)           = make_float2(c0, c1);
            *reinterpret_cast<float2*>(dst + 8 * SSP) = make_float2(c2, c3);
        }
    }
    __syncthreads();

    // ---------------- register-resident epilogue: warp w -> rows 2w, 2w+1 -----
    const float NEG_INF = __int_as_float(0xff800000);
    #pragma unroll
    for (int rr = 0; rr < 2; ++rr) {
        const int r = w * 2 + rr;
        const float* row = sS + r * SSP;
        const size_t gbase = ((size_t)(b * S_T + (t0 + r))) * S_IN;

        float4 v[16];
        float s = 0.f;
        #pragma unroll
        for (int i = 0; i < 16; ++i) {
            v[i] = *reinterpret_cast<const float4*>(row + i * 128 + l * 4);
            s += (v[i].x + v[i].y) + (v[i].z + v[i].w);
        }
        s = warp_sum(s);
        const float mean = s * (1.0f / 2048.0f);

        float m = NEG_INF;
        #pragma unroll
        for (int i = 0; i < 16; ++i) {
            const unsigned int mk = *reinterpret_cast<const unsigned int*>(
                msk + gbase + i * 128 + l * 4);
            v[i].x = fabsf(v[i].x - mean);
            v[i].y = fabsf(v[i].y - mean);
            v[i].z = fabsf(v[i].z - mean);
            v[i].w = fabsf(v[i].w - mean);
            if (mk & 0x000000FFu) v[i].x = NEG_INF;
            if (mk & 0x0000FF00u) v[i].y = NEG_INF;
            if (mk & 0x00FF0000u) v[i].z = NEG_INF;
            if (mk & 0xFF000000u) v[i].w = NEG_INF;
            m = fmaxf(m, fmaxf(fmaxf(v[i].x, v[i].y), fmaxf(v[i].z, v[i].w)));
        }
        m = warp_max(m);

        float lsum = 0.f;
        #pragma unroll
        for (int i = 0; i < 16; ++i) {
            v[i].x = __expf(v[i].x - m);
            v[i].y = __expf(v[i].y - m);
            v[i].z = __expf(v[i].z - m);
            v[i].w = __expf(v[i].w - m);
            lsum += (v[i].x + v[i].y) + (v[i].z + v[i].w);
        }
        lsum = warp_sum(lsum);
        const float inv = 1.0f / lsum;

        #pragma unroll
        for (int i = 0; i < 16; ++i) {
            v[i].x *= inv; v[i].y *= inv; v[i].z *= inv; v[i].w *= inv;
            *reinterpret_cast<float4*>(out + gbase + i * 128 + l * 4) = v[i];
        }
    }
}

extern "C" void kernel_launch(void* const* d_in, const int* in_sizes, int n_in,
                              void* d_out, int out_size)
{
    const float*         inp  = (const float*)d_in[0];
    const float*         tgt  = (const float*)d_in[1];
    const unsigned char* msk  = (const unsigned char*)d_in[2];
    const float*         Wm   = (const float*)d_in[3];
    const float*         bias = (const float*)d_in[4];
    float*               out  = (float*)d_out;

    const int smem_bytes = SMEM_FLOATS * (int)sizeof(float); // ~170 KB
    cudaFuncSetAttribute(attn_mma_kernel,
                         cudaFuncAttributeMaxDynamicSharedMemorySize, smem_bytes);

    dim3 grid(BATCH * (S_T / TM));  // 1024 CTAs
    dim3 block(THREADS);
    attn_mma_kernel<<<grid, block, smem_bytes>>>(inp, tgt, msk, Wm, bias, out);
}

// round 14
// speedup vs baseline: 1.9154x; 1.9154x over previous
#include <cuda_runtime.h>
#include <cstdint>

// Shapes (fixed by the problem)
#define S_IN   2048
#define S_T    2048
#define BATCH  8
#define HID    64

#define TM      16           // t-rows per CTA
#define THREADS 256          // 8 warps; warp w owns s-cols {j*64 + w*8 .. +7}, j=0..31
#define SSP     2056         // sS pitch (floats)
#define LPITCH  68           // sWT staging pitch
#define BP      68           // per-warp B staging pitch (conflict-free frag LDS)

// SMEM (floats): sS[16][SSP] | sP[16][64] | stage[8 warps][8][BP]
#define SS_FLOATS   (TM * SSP)
#define SP_OFF      SS_FLOATS
#define STAGE_OFF   (SP_OFF + TM * HID)
#define SMEM_FLOATS (STAGE_OFF + 8 * 8 * BP)

__device__ __forceinline__ float tf32_hi(float x) {
    uint32_t u;
    asm("cvt.rna.tf32.f32 %0, %1;" : "=r"(u) : "f"(x));
    return __uint_as_float(u);
}

// D = A(16x8,row) * B(8x8,col) + D, tf32 inputs, f32 accum
__device__ __forceinline__ void mma8(float c[4], const float a[4], float b0, float b1) {
    asm volatile(
        "mma.sync.aligned.m16n8k8.row.col.f32.tf32.tf32.f32 "
        "{%0,%1,%2,%3}, {%4,%5,%6,%7}, {%8,%9}, {%0,%1,%2,%3};"
        : "+f"(c[0]), "+f"(c[1]), "+f"(c[2]), "+f"(c[3])
        : "r"(__float_as_uint(a[0])), "r"(__float_as_uint(a[1])),
          "r"(__float_as_uint(a[2])), "r"(__float_as_uint(a[3])),
          "r"(__float_as_uint(b0)),  "r"(__float_as_uint(b1)));
}

__device__ __forceinline__ float warp_sum(float v) {
    v += __shfl_xor_sync(0xffffffffu, v, 16);
    v += __shfl_xor_sync(0xffffffffu, v, 8);
    v += __shfl_xor_sync(0xffffffffu, v, 4);
    v += __shfl_xor_sync(0xffffffffu, v, 2);
    v += __shfl_xor_sync(0xffffffffu, v, 1);
    return v;
}
__device__ __forceinline__ float warp_max(float v) {
    v = fmaxf(v, __shfl_xor_sync(0xffffffffu, v, 16));
    v = fmaxf(v, __shfl_xor_sync(0xffffffffu, v, 8));
    v = fmaxf(v, __shfl_xor_sync(0xffffffffu, v, 4));
    v = fmaxf(v, __shfl_xor_sync(0xffffffffu, v, 2));
    v = fmaxf(v, __shfl_xor_sync(0xffffffffu, v, 1));
    return v;
}

__global__ void __launch_bounds__(THREADS, 1)
attn_mma_kernel(const float* __restrict__ inp,        // (S_IN, B, H)
                const float* __restrict__ tgt,        // (S_T, B, H)
                const unsigned char* __restrict__ msk,// (B, S_T, S_IN) bool
                const float* __restrict__ Wm,         // (H, H)  W[o][h]
                const float* __restrict__ bias,       // (H)
                float* __restrict__ out)              // (B, S_T, S_IN)
{
    extern __shared__ float sm[];
    float* sS = sm;                     // scores, pitch SSP
    float* sP = sm + SP_OFF;            // P = tgt_tile @ W^T + b, [16][64]
    float* sStage = sm + STAGE_OFF;     // per-warp B slots [8][8][BP]

    const int tid  = threadIdx.x;
    const int w    = tid >> 5;
    const int l    = tid & 31;
    const int b    = blockIdx.x >> 7;
    const int t0   = (blockIdx.x & 127) << 4;

    // ---------------- linear stage: P = tgt_tile @ W^T + bias -----------------
    {
        float* sWT = sS;                 // [64][LPITCH]
        float* sTg = sS + HID * LPITCH;  // [16][64]
        const int o  = tid >> 2;
        const int hq = (tid & 3) * 16;
        #pragma unroll
        for (int k = 0; k < 4; ++k) {
            float4 wv = *reinterpret_cast<const float4*>(Wm + o * HID + hq + 4 * k);
            sWT[(hq + 4 * k + 0) * LPITCH + o] = wv.x;
            sWT[(hq + 4 * k + 1) * LPITCH + o] = wv.y;
            sWT[(hq + 4 * k + 2) * LPITCH + o] = wv.z;
            sWT[(hq + 4 * k + 3) * LPITCH + o] = wv.w;
        }
        const int r  = tid >> 4;
        const int hh = (tid & 15) * 4;
        *reinterpret_cast<float4*>(sTg + r * HID + hh) =
            *reinterpret_cast<const float4*>(tgt + ((size_t)((t0 + r) * BATCH + b)) * HID + hh);
        __syncthreads();

        const int o0 = (tid & 15) * 4;
        float4 acc = *reinterpret_cast<const float4*>(bias + o0);
        #pragma unroll
        for (int h = 0; h < HID; ++h) {
            const float  tv = sTg[r * HID + h];
            const float4 wv = *reinterpret_cast<const float4*>(sWT + h * LPITCH + o0);
            acc.x += tv * wv.x;
            acc.y += tv * wv.y;
            acc.z += tv * wv.z;
            acc.w += tv * wv.w;
        }
        *reinterpret_cast<float4*>(sP + r * HID + o0) = acc;
        __syncthreads();   // P visible; sS region free for scores
    }

    // ---------------- preload A fragments (hi/lo tf32 split) ------------------
    // a0=(r,l%4) a1=(r+8,l%4) a2=(r,l%4+4) a3=(r+8,l%4+4), r = l/4, k-block kk
    float ah[8][4], al[8][4];
    {
        const float* p0 = sP + (l >> 2) * HID;
        const float* p1 = p0 + 8 * HID;
        #pragma unroll
        for (int kk = 0; kk < 8; ++kk) {
            const int k0 = kk * 8 + (l & 3);
            const float a0 = p0[k0], a1 = p1[k0], a2 = p0[k0 + 4], a3 = p1[k0 + 4];
            ah[kk][0] = tf32_hi(a0); al[kk][0] = a0 - ah[kk][0];
            ah[kk][1] = tf32_hi(a1); al[kk][1] = a1 - ah[kk][1];
            ah[kk][2] = tf32_hi(a2); al[kk][2] = a2 - ah[kk][2];
            ah[kk][3] = tf32_hi(a3); al[kk][3] = a3 - ah[kk][3];
        }
    }

    // ---------------- score GEMM: 32 tiles of 8 s-cols per warp ---------------
    float* slot = sStage + w * (8 * BP);
    const int rr4 = l >> 2;              // staging/frag row 0..7
    const int hq4 = (l & 3) * 16;        // 16-float h range owned for LDG/STS

    float4 pf[4];
    {   // prefetch tile 0: s = w*8 + row
        const float4* src = reinterpret_cast<const float4*>(
            inp + ((size_t)((w * 8 + rr4) * BATCH + b)) * HID + hq4);
        #pragma unroll
        for (int q = 0; q < 4; ++q) pf[q] = src[q];
    }

    #pragma unroll 4
    for (int j = 0; j < 32; ++j) {
        __syncwarp();                    // prior frag LDS done before overwrite
        #pragma unroll
        for (int q = 0; q < 4; ++q)
            *reinterpret_cast<float4*>(slot + rr4 * BP + hq4 + 4 * q) = pf[q];
        __syncwarp();
        if (j + 1 < 32) {               // prefetch next tile under the MMAs
            const int s = (j + 1) * 64 + w * 8 + rr4;
            const float4* src = reinterpret_cast<const float4*>(
                inp + ((size_t)(s * BATCH + b)) * HID + hq4);
            #pragma unroll
            for (int q = 0; q < 4; ++q) pf[q] = src[q];
        }

        // load fragment + precompute tf32 splits (ALU burst, outside MMA run)
        float bh0[8], bl0[8], bh1[8], bl1[8];
        const float* bp = slot + rr4 * BP + (l & 3);
        #pragma unroll
        for (int kk = 0; kk < 8; ++kk) {
            const float b0 = bp[kk * 8];
            const float b1 = bp[kk * 8 + 4];
            bh0[kk] = tf32_hi(b0);  bl0[kk] = b0 - bh0[kk];
            bh1[kk] = tf32_hi(b1);  bl1[kk] = b1 - bh1[kk];
        }

        // 3 independent accumulator chains, interleaved kk-by-kk:
        // dependent MMA of each chain arrives 3 issue slots later -> RAW hidden
        float chh[4] = {0.f, 0.f, 0.f, 0.f};
        float clh[4] = {0.f, 0.f, 0.f, 0.f};
        float chl[4] = {0.f, 0.f, 0.f, 0.f};
        #pragma unroll
        for (int kk = 0; kk < 8; ++kk) {
            mma8(chh, ah[kk], bh0[kk], bh1[kk]);   // hi*hi
            mma8(clh, al[kk], bh0[kk], bh1[kk]);   // lo*hi
            mma8(chl, ah[kk], bl0[kk], bl1[kk]);   // hi*lo
        }

        // combine + store: c0,c1 -> row l/4; c2,c3 -> row l/4+8
        const float c0 = chh[0] + clh[0] + chl[0];
        const float c1 = chh[1] + clh[1] + chl[1];
        const float c2 = chh[2] + clh[2] + chl[2];
        const float c3 = chh[3] + clh[3] + chl[3];
        float* dst = sS + rr4 * SSP + j * 64 + w * 8 + 2 * (l & 3);
        *reinterpret_cast<float2*>(dst)            = make_float2(c0, c1);
        *reinterpret_cast<float2*>(dst + 8 * SSP)  = make_float2(c2, c3);
    }
    __syncthreads();

    // ---------------- register-resident epilogue: warp w -> rows 2w, 2w+1 -----
    const float NEG_INF = __int_as_float(0xff800000);
    #pragma unroll
    for (int rr = 0; rr < 2; ++rr) {
        const int r = w * 2 + rr;
        const float* row = sS + r * SSP;
        const size_t gbase = ((size_t)(b * S_T + (t0 + r))) * S_IN;

        float4 v[16];
        float s = 0.f;
        #pragma unroll
        for (int i = 0; i < 16; ++i) {
            v[i] = *reinterpret_cast<const float4*>(row + i * 128 + l * 4);
            s += (v[i].x + v[i].y) + (v[i].z + v[i].w);
        }
        s = warp_sum(s);
        const float mean = s * (1.0f / 2048.0f);

        float m = NEG_INF;
        #pragma unroll
        for (int i = 0; i < 16; ++i) {
            const unsigned int mk = *reinterpret_cast<const unsigned int*>(
                msk + gbase + i * 128 + l * 4);
            v[i].x = fabsf(v[i].x - mean);
            v[i].y = fabsf(v[i].y - mean);
            v[i].z = fabsf(v[i].z - mean);
            v[i].w = fabsf(v[i].w - mean);
            if (mk & 0x000000FFu) v[i].x = NEG_INF;
            if (mk & 0x0000FF00u) v[i].y = NEG_INF;
            if (mk & 0x00FF0000u) v[i].z = NEG_INF;
            if (mk & 0xFF000000u) v[i].w = NEG_INF;
            m = fmaxf(m, fmaxf(fmaxf(v[i].x, v[i].y), fmaxf(v[i].z, v[i].w)));
        }
        m = warp_max(m);

        float lsum = 0.f;
        #pragma unroll
        for (int i = 0; i < 16; ++i) {
            v[i].x = __expf(v[i].x - m);
            v[i].y = __expf(v[i].y - m);
            v[i].z = __expf(v[i].z - m);
            v[i].w = __expf(v[i].w - m);
            lsum += (v[i].x + v[i].y) + (v[i].z + v[i].w);
        }
        lsum = warp_sum(lsum);
        const float inv = 1.0f / lsum;

        #pragma unroll
        for (int i = 0; i < 16; ++i) {
            v[i].x *= inv; v[i].y *= inv; v[i].z *= inv; v[i].w *= inv;
            *reinterpret_cast<float4*>(out + gbase + i * 128 + l * 4) = v[i];
        }
    }
}

extern "C" void kernel_launch(void* const* d_in, const int* in_sizes, int n_in,
                              void* d_out, int out_size)
{
    const float*         inp  = (const float*)d_in[0];
    const float*         tgt  = (const float*)d_in[1];
    const unsigned char* msk  = (const unsigned char*)d_in[2];
    const float*         Wm   = (const float*)d_in[3];
    const float*         bias = (const float*)d_in[4];
    float*               out  = (float*)d_out;

    const int smem_bytes = SMEM_FLOATS * (int)sizeof(float); // ~153 KB
    cudaFuncSetAttribute(attn_mma_kernel,
                         cudaFuncAttributeMaxDynamicSharedMemorySize, smem_bytes);

    dim3 grid(BATCH * (S_T / TM));  // 1024 CTAs
    dim3 block(THREADS);
    attn_mma_kernel<<<grid, block, smem_bytes>>>(inp, tgt, msk, Wm, bias, out);
}

// round 15
// speedup vs baseline: 2.1533x; 1.1242x over previous
#include <cuda_runtime.h>
#include <cstdint>

// Shapes (fixed by the problem)
#define S_IN   2048
#define S_T    2048
#define BATCH  8
#define HID    64

#define TM      16           // t-rows per CTA
#define THREADS 256          // 8 warps; warp w owns s-cols {j*64 + w*8 .. +7}, j=0..31
#define SSP     2056         // sS pitch (floats)
#define LPITCH  68           // sWT staging pitch
#define BP      68           // per-warp B staging pitch (conflict-free frag LDS)

// SMEM (floats): sS[16][SSP] | sP[16][64] | stage[8 warps][2 bufs][8][BP]
#define SS_FLOATS   (TM * SSP)
#define SP_OFF      SS_FLOATS
#define STAGE_OFF   (SP_OFF + TM * HID)
#define SMEM_FLOATS (STAGE_OFF + 8 * 2 * 8 * BP)

__device__ __forceinline__ float tf32_hi(float x) {
    uint32_t u;
    asm("cvt.rna.tf32.f32 %0, %1;" : "=r"(u) : "f"(x));
    return __uint_as_float(u);
}

__device__ __forceinline__ uint32_t smem_u32_of(const void* p) {
    uint32_t a;
    asm("{ .reg .u64 t; cvta.to.shared.u64 t, %1; cvt.u32.u64 %0, t; }" : "=r"(a) : "l"(p));
    return a;
}
__device__ __forceinline__ void cp16(uint32_t dst, const void* src) {
    asm volatile("cp.async.cg.shared.global [%0], [%1], 16;" :: "r"(dst), "l"(src) : "memory");
}
__device__ __forceinline__ void cp_commit() {
    asm volatile("cp.async.commit_group;" ::: "memory");
}
__device__ __forceinline__ void cp_wait1() {
    asm volatile("cp.async.wait_group 1;" ::: "memory");
}
__device__ __forceinline__ void cp_wait0() {
    asm volatile("cp.async.wait_group 0;" ::: "memory");
}

// D = A(16x8,row) * B(8x8,col) + D, tf32 inputs, f32 accum
__device__ __forceinline__ void mma8(float c[4], const float a[4], float b0, float b1) {
    asm volatile(
        "mma.sync.aligned.m16n8k8.row.col.f32.tf32.tf32.f32 "
        "{%0,%1,%2,%3}, {%4,%5,%6,%7}, {%8,%9}, {%0,%1,%2,%3};"
        : "+f"(c[0]), "+f"(c[1]), "+f"(c[2]), "+f"(c[3])
        : "r"(__float_as_uint(a[0])), "r"(__float_as_uint(a[1])),
          "r"(__float_as_uint(a[2])), "r"(__float_as_uint(a[3])),
          "r"(__float_as_uint(b0)),  "r"(__float_as_uint(b1)));
}

__device__ __forceinline__ float warp_sum(float v) {
    v += __shfl_xor_sync(0xffffffffu, v, 16);
    v += __shfl_xor_sync(0xffffffffu, v, 8);
    v += __shfl_xor_sync(0xffffffffu, v, 4);
    v += __shfl_xor_sync(0xffffffffu, v, 2);
    v += __shfl_xor_sync(0xffffffffu, v, 1);
    return v;
}
__device__ __forceinline__ float warp_max(float v) {
    v = fmaxf(v, __shfl_xor_sync(0xffffffffu, v, 16));
    v = fmaxf(v, __shfl_xor_sync(0xffffffffu, v, 8));
    v = fmaxf(v, __shfl_xor_sync(0xffffffffu, v, 4));
    v = fmaxf(v, __shfl_xor_sync(0xffffffffu, v, 2));
    v = fmaxf(v, __shfl_xor_sync(0xffffffffu, v, 1));
    return v;
}

__global__ void __launch_bounds__(THREADS, 1)
attn_mma_kernel(const float* __restrict__ inp,        // (S_IN, B, H)
                const float* __restrict__ tgt,        // (S_T, B, H)
                const unsigned char* __restrict__ msk,// (B, S_T, S_IN) bool
                const float* __restrict__ Wm,         // (H, H)  W[o][h]
                const float* __restrict__ bias,       // (H)
                float* __restrict__ out)              // (B, S_T, S_IN)
{
    extern __shared__ float sm[];
    float* sS = sm;                     // scores, pitch SSP
    float* sP = sm + SP_OFF;            // P = tgt_tile @ W^T + b, [16][64]
    float* sStage = sm + STAGE_OFF;     // per-warp double-buffered B slots

    const int tid  = threadIdx.x;
    const int w    = tid >> 5;
    const int l    = tid & 31;
    const int b    = blockIdx.x >> 7;
    const int t0   = (blockIdx.x & 127) << 4;

    // ---------------- linear stage: P = tgt_tile @ W^T + bias -----------------
    {
        float* sWT = sS;                 // [64][LPITCH]
        float* sTg = sS + HID * LPITCH;  // [16][64]
        const int o  = tid >> 2;
        const int hq = (tid & 3) * 16;
        #pragma unroll
        for (int k = 0; k < 4; ++k) {
            float4 wv = *reinterpret_cast<const float4*>(Wm + o * HID + hq + 4 * k);
            sWT[(hq + 4 * k + 0) * LPITCH + o] = wv.x;
            sWT[(hq + 4 * k + 1) * LPITCH + o] = wv.y;
            sWT[(hq + 4 * k + 2) * LPITCH + o] = wv.z;
            sWT[(hq + 4 * k + 3) * LPITCH + o] = wv.w;
        }
        const int r  = tid >> 4;
        const int hh = (tid & 15) * 4;
        *reinterpret_cast<float4*>(sTg + r * HID + hh) =
            *reinterpret_cast<const float4*>(tgt + ((size_t)((t0 + r) * BATCH + b)) * HID + hh);
        __syncthreads();

        const int o0 = (tid & 15) * 4;
        float4 acc = *reinterpret_cast<const float4*>(bias + o0);
        #pragma unroll
        for (int h = 0; h < HID; ++h) {
            const float  tv = sTg[r * HID + h];
            const float4 wv = *reinterpret_cast<const float4*>(sWT + h * LPITCH + o0);
            acc.x += tv * wv.x;
            acc.y += tv * wv.y;
            acc.z += tv * wv.z;
            acc.w += tv * wv.w;
        }
        *reinterpret_cast<float4*>(sP + r * HID + o0) = acc;
        __syncthreads();   // P visible; sS region free for scores
    }

    // ---------------- preload A fragments (hi/lo tf32 split) ------------------
    // a0=(r,l%4) a1=(r+8,l%4) a2=(r,l%4+4) a3=(r+8,l%4+4), r = l/4, k-block kk
    float ah[8][4], al[8][4];
    {
        const float* p0 = sP + (l >> 2) * HID;
        const float* p1 = p0 + 8 * HID;
        #pragma unroll
        for (int kk = 0; kk < 8; ++kk) {
            const int k0 = kk * 8 + (l & 3);
            const float a0 = p0[k0], a1 = p1[k0], a2 = p0[k0 + 4], a3 = p1[k0 + 4];
            ah[kk][0] = tf32_hi(a0); al[kk][0] = a0 - ah[kk][0];
            ah[kk][1] = tf32_hi(a1); al[kk][1] = a1 - ah[kk][1];
            ah[kk][2] = tf32_hi(a2); al[kk][2] = a2 - ah[kk][2];
            ah[kk][3] = tf32_hi(a3); al[kk][3] = a3 - ah[kk][3];
        }
    }

    // ---------------- score GEMM: 32 tiles of 8 s-cols per warp ---------------
    // Per-warp double-buffered staging, filled via cp.async (no RF round trip).
    const int rr4 = l >> 2;              // staging/frag row 0..7
    const int hq4 = (l & 3) * 16;        // 16-float h range owned for the copy
    float* slotBase = sStage + w * (2 * 8 * BP);
    const uint32_t slotU0 = smem_u32_of(slotBase);
    const uint32_t laneOff = (uint32_t)((rr4 * BP + hq4) * 4);  // byte offset in slot

    // prologue: issue tile 0 into buf 0
    {
        const float* src = inp + ((size_t)((w * 8 + rr4) * BATCH + b)) * HID + hq4;
        #pragma unroll
        for (int q = 0; q < 4; ++q) cp16(slotU0 + laneOff + 16 * q, src + 4 * q);
        cp_commit();
    }

    #pragma unroll 4
    for (int j = 0; j < 32; ++j) {
        const int buf = j & 1;
        if (j + 1 < 32) {                 // issue next tile into the other buffer
            const int s = (j + 1) * 64 + w * 8 + rr4;
            const float* src = inp + ((size_t)(s * BATCH + b)) * HID + hq4;
            const uint32_t dst = slotU0 + (uint32_t)((buf ^ 1) * 8 * BP * 4) + laneOff;
            #pragma unroll
            for (int q = 0; q < 4; ++q) cp16(dst + 16 * q, src + 4 * q);
            cp_commit();
            cp_wait1();                   // tile j's group complete (j+1 in flight)
        } else {
            cp_wait0();
        }
        __syncwarp();                     // all lanes' copies of tile j visible

        // load fragment + precompute tf32 splits (ALU burst, outside MMA run)
        float bh0[8], bl0[8], bh1[8], bl1[8];
        const float* bp = slotBase + buf * (8 * BP) + rr4 * BP + (l & 3);
        #pragma unroll
        for (int kk = 0; kk < 8; ++kk) {
            const float b0 = bp[kk * 8];
            const float b1 = bp[kk * 8 + 4];
            bh0[kk] = tf32_hi(b0);  bl0[kk] = b0 - bh0[kk];
            bh1[kk] = tf32_hi(b1);  bl1[kk] = b1 - bh1[kk];
        }

        // 3 independent accumulator chains, interleaved kk-by-kk
        float chh[4] = {0.f, 0.f, 0.f, 0.f};
        float clh[4] = {0.f, 0.f, 0.f, 0.f};
        float chl[4] = {0.f, 0.f, 0.f, 0.f};
        #pragma unroll
        for (int kk = 0; kk < 8; ++kk) {
            mma8(chh, ah[kk], bh0[kk], bh1[kk]);   // hi*hi
            mma8(clh, al[kk], bh0[kk], bh1[kk]);   // lo*hi
            mma8(chl, ah[kk], bl0[kk], bl1[kk]);   // hi*lo
        }

        // combine + store: c0,c1 -> row l/4; c2,c3 -> row l/4+8
        const float c0 = chh[0] + clh[0] + chl[0];
        const float c1 = chh[1] + clh[1] + chl[1];
        const float c2 = chh[2] + clh[2] + chl[2];
        const float c3 = chh[3] + clh[3] + chl[3];
        float* dst = sS + rr4 * SSP + j * 64 + w * 8 + 2 * (l & 3);
        *reinterpret_cast<float2*>(dst)            = make_float2(c0, c1);
        *reinterpret_cast<float2*>(dst + 8 * SSP)  = make_float2(c2, c3);
    }
    __syncthreads();

    // ---------------- register-resident epilogue: warp w -> rows 2w, 2w+1 -----
    const float NEG_INF = __int_as_float(0xff800000);
    #pragma unroll
    for (int rr = 0; rr < 2; ++rr) {
        const int r = w * 2 + rr;
        const float* row = sS + r * SSP;
        const size_t gbase = ((size_t)(b * S_T + (t0 + r))) * S_IN;

        float4 v[16];
        float s = 0.f;
        #pragma unroll
        for (int i = 0; i < 16; ++i) {
            v[i] = *reinterpret_cast<const float4*>(row + i * 128 + l * 4);
            s += (v[i].x + v[i].y) + (v[i].z + v[i].w);
        }
        s = warp_sum(s);
        const float mean = s * (1.0f / 2048.0f);

        float m = NEG_INF;
        #pragma unroll
        for (int i = 0; i < 16; ++i) {
            const unsigned int mk = *reinterpret_cast<const unsigned int*>(
                msk + gbase + i * 128 + l * 4);
            v[i].x = fabsf(v[i].x - mean);
            v[i].y = fabsf(v[i].y - mean);
            v[i].z = fabsf(v[i].z - mean);
            v[i].w = fabsf(v[i].w - mean);
            if (mk & 0x000000FFu) v[i].x = NEG_INF;
            if (mk & 0x0000FF00u) v[i].y = NEG_INF;
            if (mk & 0x00FF0000u) v[i].z = NEG_INF;
            if (mk & 0xFF000000u) v[i].w = NEG_INF;
            m = fmaxf(m, fmaxf(fmaxf(v[i].x, v[i].y), fmaxf(v[i].z, v[i].w)));
        }
        m = warp_max(m);

        float lsum = 0.f;
        #pragma unroll
        for (int i = 0; i < 16; ++i) {
            v[i].x = __expf(v[i].x - m);
            v[i].y = __expf(v[i].y - m);
            v[i].z = __expf(v[i].z - m);
            v[i].w = __expf(v[i].w - m);
            lsum += (v[i].x + v[i].y) + (v[i].z + v[i].w);
        }
        lsum = warp_sum(lsum);
        const float inv = 1.0f / lsum;

        #pragma unroll
        for (int i = 0; i < 16; ++i) {
            v[i].x *= inv; v[i].y *= inv; v[i].z *= inv; v[i].w *= inv;
            *reinterpret_cast<float4*>(out + gbase + i * 128 + l * 4) = v[i];
        }
    }
}

extern "C" void kernel_launch(void* const* d_in, const int* in_sizes, int n_in,
                              void* d_out, int out_size)
{
    const float*         inp  = (const float*)d_in[0];
    const float*         tgt  = (const float*)d_in[1];
    const unsigned char* msk  = (const unsigned char*)d_in[2];
    const float*         Wm   = (const float*)d_in[3];
    const float*         bias = (const float*)d_in[4];
    float*               out  = (float*)d_out;

    const int smem_bytes = SMEM_FLOATS * (int)sizeof(float); // ~170 KB
    cudaFuncSetAttribute(attn_mma_kernel,
                         cudaFuncAttributeMaxDynamicSharedMemorySize, smem_bytes);

    dim3 grid(BATCH * (S_T / TM));  // 1024 CTAs
    dim3 block(THREADS);
    attn_mma_kernel<<<grid, block, smem_bytes>>>(inp, tgt, msk, Wm, bias, out);
}

// round 16
// speedup vs baseline: 2.2423x; 1.0413x over previous
#include <cuda_runtime.h>
#include <cstdint>

// Shapes (fixed by the problem)
#define S_IN   2048
#define S_T    2048
#define BATCH  8
#define HID    64

#define TM      16           // t-rows per CTA
#define THREADS 512          // 16 warps; warp w owns cols {j*128 + w*8 .. +7}, j=0..15
#define NJ      16
#define SSP     2056         // sS pitch (floats)
#define LPITCH  68           // sWT staging pitch
#define BP      68           // per-warp B staging pitch (conflict-free frag LDS)

// SMEM (floats): sS[16][SSP] | sP[16][64] | stage[16 warps][2 bufs][8][BP]
#define SS_FLOATS   (TM * SSP)
#define SP_OFF      SS_FLOATS
#define STAGE_OFF   (SP_OFF + TM * HID)
#define SMEM_FLOATS (STAGE_OFF + 16 * 2 * 8 * BP)

__device__ __forceinline__ float tf32_hi(float x) {
    uint32_t u;
    asm("cvt.rna.tf32.f32 %0, %1;" : "=r"(u) : "f"(x));
    return __uint_as_float(u);
}

__device__ __forceinline__ uint32_t smem_u32_of(const void* p) {
    uint32_t a;
    asm("{ .reg .u64 t; cvta.to.shared.u64 t, %1; cvt.u32.u64 %0, t; }" : "=r"(a) : "l"(p));
    return a;
}
__device__ __forceinline__ void cp16(uint32_t dst, const void* src) {
    asm volatile("cp.async.cg.shared.global [%0], [%1], 16;" :: "r"(dst), "l"(src) : "memory");
}
__device__ __forceinline__ void cp_commit() {
    asm volatile("cp.async.commit_group;" ::: "memory");
}
__device__ __forceinline__ void cp_wait1() {
    asm volatile("cp.async.wait_group 1;" ::: "memory");
}
__device__ __forceinline__ void cp_wait0() {
    asm volatile("cp.async.wait_group 0;" ::: "memory");
}

// D = A(16x8,row) * B(8x8,col) + D, tf32 inputs, f32 accum
__device__ __forceinline__ void mma8(float c[4], const float a[4], float b0, float b1) {
    asm volatile(
        "mma.sync.aligned.m16n8k8.row.col.f32.tf32.tf32.f32 "
        "{%0,%1,%2,%3}, {%4,%5,%6,%7}, {%8,%9}, {%0,%1,%2,%3};"
        : "+f"(c[0]), "+f"(c[1]), "+f"(c[2]), "+f"(c[3])
        : "r"(__float_as_uint(a[0])), "r"(__float_as_uint(a[1])),
          "r"(__float_as_uint(a[2])), "r"(__float_as_uint(a[3])),
          "r"(__float_as_uint(b0)),  "r"(__float_as_uint(b1)));
}

__device__ __forceinline__ float warp_sum(float v) {
    v += __shfl_xor_sync(0xffffffffu, v, 16);
    v += __shfl_xor_sync(0xffffffffu, v, 8);
    v += __shfl_xor_sync(0xffffffffu, v, 4);
    v += __shfl_xor_sync(0xffffffffu, v, 2);
    v += __shfl_xor_sync(0xffffffffu, v, 1);
    return v;
}
__device__ __forceinline__ float warp_max(float v) {
    v = fmaxf(v, __shfl_xor_sync(0xffffffffu, v, 16));
    v = fmaxf(v, __shfl_xor_sync(0xffffffffu, v, 8));
    v = fmaxf(v, __shfl_xor_sync(0xffffffffu, v, 4));
    v = fmaxf(v, __shfl_xor_sync(0xffffffffu, v, 2));
    v = fmaxf(v, __shfl_xor_sync(0xffffffffu, v, 1));
    return v;
}

__global__ void __launch_bounds__(THREADS, 1)
attn_mma_kernel(const float* __restrict__ inp,        // (S_IN, B, H)
                const float* __restrict__ tgt,        // (S_T, B, H)
                const unsigned char* __restrict__ msk,// (B, S_T, S_IN) bool
                const float* __restrict__ Wm,         // (H, H)  W[o][h]
                const float* __restrict__ bias,       // (H)
                float* __restrict__ out)              // (B, S_T, S_IN)
{
    extern __shared__ float sm[];
    float* sS = sm;                     // scores, pitch SSP
    float* sP = sm + SP_OFF;            // P = tgt_tile @ W^T + b, [16][64]
    float* sStage = sm + STAGE_OFF;     // per-warp double-buffered B slots

    const int tid  = threadIdx.x;
    const int w    = tid >> 5;
    const int l    = tid & 31;
    const int b    = blockIdx.x >> 7;
    const int t0   = (blockIdx.x & 127) << 4;

    // ---------------- linear stage: P = tgt_tile @ W^T + bias -----------------
    {
        float* sWT = sS;                 // [64][LPITCH]
        float* sTg = sS + HID * LPITCH;  // [16][64]
        if (tid < 256) {
            const int o  = tid >> 2;
            const int hq = (tid & 3) * 16;
            #pragma unroll
            for (int k = 0; k < 4; ++k) {
                float4 wv = *reinterpret_cast<const float4*>(Wm + o * HID + hq + 4 * k);
                sWT[(hq + 4 * k + 0) * LPITCH + o] = wv.x;
                sWT[(hq + 4 * k + 1) * LPITCH + o] = wv.y;
                sWT[(hq + 4 * k + 2) * LPITCH + o] = wv.z;
                sWT[(hq + 4 * k + 3) * LPITCH + o] = wv.w;
            }
            const int r  = tid >> 4;
            const int hh = (tid & 15) * 4;
            *reinterpret_cast<float4*>(sTg + r * HID + hh) =
                *reinterpret_cast<const float4*>(tgt + ((size_t)((t0 + r) * BATCH + b)) * HID + hh);
        }
        __syncthreads();

        if (tid < 256) {
            const int r  = tid >> 4;
            const int o0 = (tid & 15) * 4;
            float4 acc = *reinterpret_cast<const float4*>(bias + o0);
            #pragma unroll
            for (int h = 0; h < HID; ++h) {
                const float  tv = sTg[r * HID + h];
                const float4 wv = *reinterpret_cast<const float4*>(sWT + h * LPITCH + o0);
                acc.x += tv * wv.x;
                acc.y += tv * wv.y;
                acc.z += tv * wv.z;
                acc.w += tv * wv.w;
            }
            *reinterpret_cast<float4*>(sP + r * HID + o0) = acc;
        }
        __syncthreads();   // P visible; sS region free for scores
    }

    // ---------------- preload A fragments (hi/lo tf32 split) ------------------
    // a0=(r,l%4) a1=(r+8,l%4) a2=(r,l%4+4) a3=(r+8,l%4+4), r = l/4, k-block kk
    float ah[8][4], al[8][4];
    {
        const float* p0 = sP + (l >> 2) * HID;
        const float* p1 = p0 + 8 * HID;
        #pragma unroll
        for (int kk = 0; kk < 8; ++kk) {
            const int k0 = kk * 8 + (l & 3);
            const float a0 = p0[k0], a1 = p1[k0], a2 = p0[k0 + 4], a3 = p1[k0 + 4];
            ah[kk][0] = tf32_hi(a0); al[kk][0] = a0 - ah[kk][0];
            ah[kk][1] = tf32_hi(a1); al[kk][1] = a1 - ah[kk][1];
            ah[kk][2] = tf32_hi(a2); al[kk][2] = a2 - ah[kk][2];
            ah[kk][3] = tf32_hi(a3); al[kk][3] = a3 - ah[kk][3];
        }
    }

    // ---------------- score GEMM: 16 tiles of 8 s-cols per warp ---------------
    // Per-warp double-buffered staging, filled via cp.async (no RF round trip).
    const int rr4 = l >> 2;              // staging/frag row 0..7
    const int hq4 = (l & 3) * 16;        // 16-float h range owned for the copy
    float* slotBase = sStage + w * (2 * 8 * BP);
    const uint32_t slotU0 = smem_u32_of(slotBase);
    const uint32_t laneOff = (uint32_t)((rr4 * BP + hq4) * 4);  // byte offset in slot

    // prologue: issue tile 0 into buf 0
    {
        const float* src = inp + ((size_t)((w * 8 + rr4) * BATCH + b)) * HID + hq4;
        #pragma unroll
        for (int q = 0; q < 4; ++q) cp16(slotU0 + laneOff + 16 * q, src + 4 * q);
        cp_commit();
    }

    #pragma unroll 4
    for (int j = 0; j < NJ; ++j) {
        const int buf = j & 1;
        if (j + 1 < NJ) {                 // issue next tile into the other buffer
            const int s = (j + 1) * 128 + w * 8 + rr4;
            const float* src = inp + ((size_t)(s * BATCH + b)) * HID + hq4;
            const uint32_t dst = slotU0 + (uint32_t)((buf ^ 1) * 8 * BP * 4) + laneOff;
            #pragma unroll
            for (int q = 0; q < 4; ++q) cp16(dst + 16 * q, src + 4 * q);
            cp_commit();
            cp_wait1();                   // tile j's group complete (j+1 in flight)
        } else {
            cp_wait0();
        }
        __syncwarp();                     // all lanes' copies of tile j visible

        // load fragment + precompute tf32 splits (ALU burst, outside MMA run)
        float bh0[8], bl0[8], bh1[8], bl1[8];
        const float* bp = slotBase + buf * (8 * BP) + rr4 * BP + (l & 3);
        #pragma unroll
        for (int kk = 0; kk < 8; ++kk) {
            const float b0 = bp[kk * 8];
            const float b1 = bp[kk * 8 + 4];
            bh0[kk] = tf32_hi(b0);  bl0[kk] = b0 - bh0[kk];
            bh1[kk] = tf32_hi(b1);  bl1[kk] = b1 - bh1[kk];
        }

        // 3 independent accumulator chains, interleaved kk-by-kk
        float chh[4] = {0.f, 0.f, 0.f, 0.f};
        float clh[4] = {0.f, 0.f, 0.f, 0.f};
        float chl[4] = {0.f, 0.f, 0.f, 0.f};
        #pragma unroll
        for (int kk = 0; kk < 8; ++kk) {
            mma8(chh, ah[kk], bh0[kk], bh1[kk]);   // hi*hi
            mma8(clh, al[kk], bh0[kk], bh1[kk]);   // lo*hi
            mma8(chl, ah[kk], bl0[kk], bl1[kk]);   // hi*lo
        }

        // combine + store: c0,c1 -> row l/4; c2,c3 -> row l/4+8
        const float c0 = chh[0] + clh[0] + chl[0];
        const float c1 = chh[1] + clh[1] + chl[1];
        const float c2 = chh[2] + clh[2] + chl[2];
        const float c3 = chh[3] + clh[3] + chl[3];
        float* dst = sS + rr4 * SSP + j * 128 + w * 8 + 2 * (l & 3);
        *reinterpret_cast<float2*>(dst)            = make_float2(c0, c1);
        *reinterpret_cast<float2*>(dst + 8 * SSP)  = make_float2(c2, c3);
    }
    __syncthreads();

    // ---------------- register-resident epilogue: warp w -> row w -------------
    const float NEG_INF = __int_as_float(0xff800000);
    {
        const int r = w;
        const float* row = sS + r * SSP;
        const size_t gbase = ((size_t)(b * S_T + (t0 + r))) * S_IN;

        float4 v[16];
        float s = 0.f;
        #pragma unroll
        for (int i = 0; i < 16; ++i) {
            v[i] = *reinterpret_cast<const float4*>(row + i * 128 + l * 4);
            s += (v[i].x + v[i].y) + (v[i].z + v[i].w);
        }
        s = warp_sum(s);
        const float mean = s * (1.0f / 2048.0f);

        float m = NEG_INF;
        #pragma unroll
        for (int i = 0; i < 16; ++i) {
            const unsigned int mk = *reinterpret_cast<const unsigned int*>(
                msk + gbase + i * 128 + l * 4);
            v[i].x = fabsf(v[i].x - mean);
            v[i].y = fabsf(v[i].y - mean);
            v[i].z = fabsf(v[i].z - mean);
            v[i].w = fabsf(v[i].w - mean);
            if (mk & 0x000000FFu) v[i].x = NEG_INF;
            if (mk & 0x0000FF00u) v[i].y = NEG_INF;
            if (mk & 0x00FF0000u) v[i].z = NEG_INF;
            if (mk & 0xFF000000u) v[i].w = NEG_INF;
            m = fmaxf(m, fmaxf(fmaxf(v[i].x, v[i].y), fmaxf(v[i].z, v[i].w)));
        }
        m = warp_max(m);

        float lsum = 0.f;
        #pragma unroll
        for (int i = 0; i < 16; ++i) {
            v[i].x = __expf(v[i].x - m);
            v[i].y = __expf(v[i].y - m);
            v[i].z = __expf(v[i].z - m);
            v[i].w = __expf(v[i].w - m);
            lsum += (v[i].x + v[i].y) + (v[i].z + v[i].w);
        }
        lsum = warp_sum(lsum);
        const float inv = 1.0f / lsum;

        #pragma unroll
        for (int i = 0; i < 16; ++i) {
            v[i].x *= inv; v[i].y *= inv; v[i].z *= inv; v[i].w *= inv;
            *reinterpret_cast<float4*>(out + gbase + i * 128 + l * 4) = v[i];
        }
    }
}

extern "C" void kernel_launch(void* const* d_in, const int* in_sizes, int n_in,
                              void* d_out, int out_size)
{
    const float*         inp  = (const float*)d_in[0];
    const float*         tgt  = (const float*)d_in[1];
    const unsigned char* msk  = (const unsigned char*)d_in[2];
    const float*         Wm   = (const float*)d_in[3];
    const float*         bias = (const float*)d_in[4];
    float*               out  = (float*)d_out;

    const int smem_bytes = SMEM_FLOATS * (int)sizeof(float); // ~200 KB
    cudaFuncSetAttribute(attn_mma_kernel,
                         cudaFuncAttributeMaxDynamicSharedMemorySize, smem_bytes);

    dim3 grid(BATCH * (S_T / TM));  // 1024 CTAs
    dim3 block(THREADS);
    attn_mma_kernel<<<grid, block, smem_bytes>>>(inp, tgt, msk, Wm, bias, out);
}